// round 4
// baseline (speedup 1.0000x reference)
#include <cuda_runtime.h>
#include <math.h>

#define B_ 256
#define V_ 128
#define M_ 256
#define H_ 1024
#define TD 10
#define IN_DIM 35840          // (V + TD + 1 + 1) * M
#define KC 4                  // split-K chunks
#define KPC (IN_DIM / KC)     // 8960
#define BM 128
#define BN 64
#define BK 32
#define PA 36                 // padded A smem pitch (floats)
#define PW 72                 // padded W smem pitch (floats)

// ---------------- device scratch (no allocations allowed) ----------------
__device__ float g_pred[B_ * IN_DIM];       // 36.7 MB, tf32-rounded features
__device__ float g_h1p[KC][B_ * H_];        // split-K partials, GEMM 1
__device__ float g_hgp[KC][B_ * H_];        // split-K partials, gate GEMM
__device__ float g_h[B_ * H_];              // gated hidden

__device__ __forceinline__ float to_tf32(float x) {
    unsigned u = __float_as_uint(x), r;
    asm("cvt.rna.tf32.f32 %0, %1;" : "=r"(r) : "r"(u));
    return __uint_as_float(r);
}

__device__ __forceinline__ void mma8(float c[4], const unsigned a[4],
                                     unsigned b0, unsigned b1) {
    asm volatile(
        "mma.sync.aligned.m16n8k8.row.col.f32.tf32.tf32.f32 "
        "{%0,%1,%2,%3}, {%4,%5,%6,%7}, {%8,%9}, {%0,%1,%2,%3};\n"
        : "+f"(c[0]), "+f"(c[1]), "+f"(c[2]), "+f"(c[3])
        : "r"(a[0]), "r"(a[1]), "r"(a[2]), "r"(a[3]), "r"(b0), "r"(b1));
}

// ---------------- kernel 1: preprocessing (roll + stable sort + features) ---
__global__ __launch_bounds__(256) void prep_kernel(
    const float* __restrict__ x, const float* __restrict__ memory,
    const void* __restrict__ timings_raw, const float* __restrict__ msurp,
    const float* __restrict__ lastpred) {
    int b = blockIdx.x, s = threadIdx.x;
    __shared__ int t_sh[M_];
    __shared__ int rank_sh[M_];
    __shared__ float red[256];
    __shared__ int hi_nonzero;

    if (s == 0) hi_nonzero = 0;
    __syncthreads();
    // dtype sniff: int64 -> high 32-bit words of first 256 entries are all 0
    {
        const unsigned* w32 = (const unsigned*)timings_raw;
        if (w32[2 * s + 1] != 0u) hi_nonzero = 1;
    }
    __syncthreads();
    int is64 = !hi_nonzero;

    // rolled timings: slot 0 = 0 (new token), slot s = old[s-1] + 1
    int t;
    if (s == 0) {
        t = 0;
    } else {
        int src = b * M_ + s - 1;
        long long tv = is64 ? ((const long long*)timings_raw)[src]
                            : (long long)((const int*)timings_raw)[src];
        t = (int)tv + 1;
    }
    t_sh[s] = t;
    __syncthreads();

    // stable ascending rank + max (O(M) per thread)
    int r = 0, mx = 0;
#pragma unroll 8
    for (int j = 0; j < M_; ++j) {
        int tj = t_sh[j];
        mx = max(mx, tj);
        r += (tj < t) || (tj == t && j < s);
    }
    rank_sh[s] = r;

    // surprise = -log(dot(x, last_prediction) + 1e-8)
    float pv = (s < V_) ? x[b * V_ + s] * lastpred[b * V_ + s] : 0.f;
    red[s] = pv;
    __syncthreads();
    for (int off = 128; off; off >>= 1) {
        if (s < off) red[s] += red[s + off];
        __syncthreads();
    }
    float surprise = -logf(red[0] + 1e-8f);

    float invd = 1.f / ((float)mx + 1.f);
    float* base = g_pred + (size_t)b * IN_DIM;

    // timing bits, normalized timing, surprise (scattered by sorted rank)
#pragma unroll
    for (int d = 0; d < TD; ++d)
        base[M_ * V_ + r * TD + d] = (float)((t >> d) & 1);
    base[M_ * V_ + M_ * TD + r] = to_tf32((float)t * invd);
    float sv = (s == 0) ? surprise : msurp[b * M_ + s - 1] * 0.99f;
    base[M_ * V_ + M_ * TD + M_ + r] = to_tf32(sv);

    // gather memory rows into sorted order (tf32-rounded)
    for (int e = s; e < M_ * V_; e += 256) {
        int sl = e >> 7, v = e & (V_ - 1);
        float val = sl ? memory[((size_t)(b * M_ + sl - 1)) * V_ + v]
                       : x[b * V_ + v];
        base[rank_sh[sl] * V_ + v] = to_tf32(val);
    }
}

// ---------------- kernel 2: fused dual TF32 GEMM, split-K -------------------
__global__ __launch_bounds__(256) void gemm_kernel(
    const float* __restrict__ W1, const float* __restrict__ Wg) {
    __shared__ __align__(16) float As[BM * PA];
    __shared__ __align__(16) float Bs1[BK * PW];
    __shared__ __align__(16) float Bsg[BK * PW];

    int tid = threadIdx.x, lane = tid & 31, warp = tid >> 5;
    int wm = warp >> 1, wn = warp & 1;        // 4x2 warp grid, warp tile 32x32
    int n0 = blockIdx.x * BN;
    int bm0 = blockIdx.y * BM;
    int z = blockIdx.z;
    int k0 = z * KPC;
    int g = lane >> 2, q = lane & 3;

    float acc1[2][4][4], accg[2][4][4];
#pragma unroll
    for (int mf = 0; mf < 2; ++mf)
#pragma unroll
        for (int nf = 0; nf < 4; ++nf)
#pragma unroll
            for (int i = 0; i < 4; ++i) { acc1[mf][nf][i] = 0.f; accg[mf][nf][i] = 0.f; }

    // load index precompute
    int arow[4], ac4[4], wkr[2], wc4[2];
#pragma unroll
    for (int i = 0; i < 4; ++i) { int idx = tid + i * 256; arow[i] = idx >> 3; ac4[i] = idx & 7; }
#pragma unroll
    for (int i = 0; i < 2; ++i) { int idx = tid + i * 256; wkr[i] = idx >> 4; wc4[i] = idx & 15; }

    float4 ar[4], w1r[2], wgr[2];
    // initial tile load
#pragma unroll
    for (int i = 0; i < 4; ++i)
        ar[i] = *(const float4*)(g_pred + (size_t)(bm0 + arow[i]) * IN_DIM + k0 + ac4[i] * 4);
#pragma unroll
    for (int i = 0; i < 2; ++i) {
        w1r[i] = *(const float4*)(W1 + (size_t)(k0 + wkr[i]) * H_ + n0 + wc4[i] * 4);
        wgr[i] = *(const float4*)(Wg + (size_t)(k0 + wkr[i]) * H_ + n0 + wc4[i] * 4);
    }

    const int NITER = KPC / BK;  // 280
    for (int kb = 0; kb < NITER; ++kb) {
        // regs -> smem (A already tf32; W rounded here)
#pragma unroll
        for (int i = 0; i < 4; ++i)
            *(float4*)(As + arow[i] * PA + ac4[i] * 4) = ar[i];
#pragma unroll
        for (int i = 0; i < 2; ++i) {
            float4 v = w1r[i];
            v.x = to_tf32(v.x); v.y = to_tf32(v.y); v.z = to_tf32(v.z); v.w = to_tf32(v.w);
            *(float4*)(Bs1 + wkr[i] * PW + wc4[i] * 4) = v;
            float4 u = wgr[i];
            u.x = to_tf32(u.x); u.y = to_tf32(u.y); u.z = to_tf32(u.z); u.w = to_tf32(u.w);
            *(float4*)(Bsg + wkr[i] * PW + wc4[i] * 4) = u;
        }
        __syncthreads();

        // prefetch next tile while computing
        if (kb + 1 < NITER) {
            int kt = k0 + (kb + 1) * BK;
#pragma unroll
            for (int i = 0; i < 4; ++i)
                ar[i] = *(const float4*)(g_pred + (size_t)(bm0 + arow[i]) * IN_DIM + kt + ac4[i] * 4);
#pragma unroll
            for (int i = 0; i < 2; ++i) {
                w1r[i] = *(const float4*)(W1 + (size_t)(kt + wkr[i]) * H_ + n0 + wc4[i] * 4);
                wgr[i] = *(const float4*)(Wg + (size_t)(kt + wkr[i]) * H_ + n0 + wc4[i] * 4);
            }
        }

#pragma unroll
        for (int kk = 0; kk < 4; ++kk) {
            unsigned a[2][4];
#pragma unroll
            for (int mf = 0; mf < 2; ++mf) {
                const float* ap = As + (wm * 32 + mf * 16) * PA + kk * 8 + q;
                a[mf][0] = __float_as_uint(ap[g * PA]);
                a[mf][1] = __float_as_uint(ap[(g + 8) * PA]);
                a[mf][2] = __float_as_uint(ap[g * PA + 4]);
                a[mf][3] = __float_as_uint(ap[(g + 8) * PA + 4]);
            }
            unsigned b1f[4][2], bgf[4][2];
#pragma unroll
            for (int nf = 0; nf < 4; ++nf) {
                int col = wn * 32 + nf * 8 + g;
                b1f[nf][0] = __float_as_uint(Bs1[(kk * 8 + q) * PW + col]);
                b1f[nf][1] = __float_as_uint(Bs1[(kk * 8 + q + 4) * PW + col]);
                bgf[nf][0] = __float_as_uint(Bsg[(kk * 8 + q) * PW + col]);
                bgf[nf][1] = __float_as_uint(Bsg[(kk * 8 + q + 4) * PW + col]);
            }
#pragma unroll
            for (int mf = 0; mf < 2; ++mf)
#pragma unroll
                for (int nf = 0; nf < 4; ++nf) {
                    mma8(acc1[mf][nf], a[mf], b1f[nf][0], b1f[nf][1]);
                    mma8(accg[mf][nf], a[mf], bgf[nf][0], bgf[nf][1]);
                }
        }
        __syncthreads();
    }

    // epilogue: deterministic per-chunk partial writes (no atomics)
    float* o1 = g_h1p[z];
    float* og = g_hgp[z];
#pragma unroll
    for (int mf = 0; mf < 2; ++mf)
#pragma unroll
        for (int nf = 0; nf < 4; ++nf) {
            int row = bm0 + wm * 32 + mf * 16 + g;
            int col = n0 + wn * 32 + nf * 8 + 2 * q;
            o1[(size_t)row * H_ + col]           = acc1[mf][nf][0];
            o1[(size_t)row * H_ + col + 1]       = acc1[mf][nf][1];
            o1[(size_t)(row + 8) * H_ + col]     = acc1[mf][nf][2];
            o1[(size_t)(row + 8) * H_ + col + 1] = acc1[mf][nf][3];
            og[(size_t)row * H_ + col]           = accg[mf][nf][0];
            og[(size_t)row * H_ + col + 1]       = accg[mf][nf][1];
            og[(size_t)(row + 8) * H_ + col]     = accg[mf][nf][2];
            og[(size_t)(row + 8) * H_ + col + 1] = accg[mf][nf][3];
        }
}

// ---------------- kernel 3: split-K reduce + bias + gate --------------------
__global__ __launch_bounds__(256) void gate_kernel(
    const float* __restrict__ b1, const float* __restrict__ bg) {
    int idx = blockIdx.x * 256 + threadIdx.x;  // grid 1024 -> 262144
    float s1 = g_h1p[0][idx] + g_h1p[1][idx] + g_h1p[2][idx] + g_h1p[3][idx];
    float sg = g_hgp[0][idx] + g_hgp[1][idx] + g_hgp[2][idx] + g_hgp[3][idx];
    int j = idx & (H_ - 1);
    float pre = s1 + b1[j];
    float gv = sg + bg[j];
    g_h[idx] = pre * (1.f / (1.f + expf(-gv)));
}

// ---------------- kernel 4: h @ W2 + b2 (fp32, small) -----------------------
__global__ __launch_bounds__(128) void out_kernel(
    const float* __restrict__ W2, const float* __restrict__ b2,
    float* __restrict__ out) {
    __shared__ float hs[H_];
    int b = blockIdx.x, v = threadIdx.x;
    for (int i = v; i < H_; i += 128) hs[i] = g_h[b * H_ + i];
    __syncthreads();
    float a0 = 0.f, a1 = 0.f, a2 = 0.f, a3 = 0.f;
#pragma unroll 8
    for (int k = 0; k < H_; k += 4) {
        a0 += hs[k]     * W2[(k)     * V_ + v];
        a1 += hs[k + 1] * W2[(k + 1) * V_ + v];
        a2 += hs[k + 2] * W2[(k + 2) * V_ + v];
        a3 += hs[k + 3] * W2[(k + 3) * V_ + v];
    }
    out[b * V_ + v] = b2[v] + ((a0 + a1) + (a2 + a3));
}

// ---------------- launch ----------------------------------------------------
extern "C" void kernel_launch(void* const* d_in, const int* in_sizes, int n_in,
                              void* d_out, int out_size) {
    const float* x        = (const float*)d_in[0];
    const float* memory   = (const float*)d_in[1];
    const void*  timings  = d_in[2];   // int32 or int64, sniffed on device
    const float* msurp    = (const float*)d_in[3];
    const float* lastpred = (const float*)d_in[4];
    const float* W1       = (const float*)d_in[5];
    const float* b1       = (const float*)d_in[6];
    const float* Wg       = (const float*)d_in[7];
    const float* bg       = (const float*)d_in[8];
    const float* W2       = (const float*)d_in[9];
    const float* b2       = (const float*)d_in[10];
    float* out = (float*)d_out;

    prep_kernel<<<B_, 256>>>(x, memory, timings, msurp, lastpred);
    gemm_kernel<<<dim3(H_ / BN, B_ / BM, KC), 256>>>(W1, Wg);
    gate_kernel<<<(B_ * H_) / 256, 256>>>(b1, bg);
    out_kernel<<<B_, 128>>>(W2, b2, out);
}